// round 15
// baseline (speedup 1.0000x reference)
#include <cuda_runtime.h>

namespace {
constexpr int IMG_W   = 512;
constexpr int OUTD    = 502;            // 512 - 11 + 1
constexpr int NIMG    = 48;
constexpr int STRIP   = 168;            // output rows per block
constexpr int NSTRIP  = 3;              // 168+168+166 → 144 blocks = ONE wave
constexpr int PITCH_U = 1042;           // ulls per ring slot row; slot stride 8336B:
                                        // 521 quads ≡ 1 (mod 8) → with slot=rq, quad ≡ t (mod 8) → conflict-free
constexpr int RING_U  = 11 * PITCH_U;   // single interleaved ring (ulls)
constexpr int STG_CH  = 11 * IMG_W;     // floats per raw channel stage
constexpr int STG_BUF = 2 * STG_CH;     // x + y (one buffer)
constexpr int NBUF    = 3;              // depth-3 staging
constexpr int NBLOCKS = NSTRIP * NIMG;  // 144
constexpr int SMEM_BYTES = RING_U * 8 + NBUF * STG_BUF * 4;  // 91696 + 135168 = 226864
constexpr float TwoC1 = 2.0e-4f;
constexpr float TwoC2 = 1.8e-3f;
}

__device__ float g_partials[NBLOCKS];
__device__ unsigned int g_done = 0;

__device__ __forceinline__ float win(int k) {
  switch (k) {
    case 0: case 10: return 0.00102838f;
    case 1: case 9:  return 0.00759873f;
    case 2: case 8:  return 0.03600078f;
    case 3: case 7:  return 0.10936070f;
    case 4: case 6:  return 0.21300553f;
    default:         return 0.26601176f;
  }
}

// ---- packed f32x2 helpers ----
__device__ __forceinline__ unsigned long long mul2(unsigned long long a, unsigned long long b) {
  unsigned long long r;
  asm("mul.rn.f32x2 %0, %1, %2;" : "=l"(r) : "l"(a), "l"(b));
  return r;
}
__device__ __forceinline__ unsigned long long add2(unsigned long long a, unsigned long long b) {
  unsigned long long r;
  asm("add.rn.f32x2 %0, %1, %2;" : "=l"(r) : "l"(a), "l"(b));
  return r;
}
__device__ __forceinline__ unsigned long long fma2(unsigned long long a, unsigned long long b,
                                                   unsigned long long c) {
  unsigned long long r;
  asm("fma.rn.f32x2 %0, %1, %2, %3;" : "=l"(r) : "l"(a), "l"(b), "l"(c));
  return r;
}
__device__ __forceinline__ unsigned long long pack2f(float lo, float hi) {
  unsigned long long r;
  asm("mov.b64 %0, {%1, %2};" : "=l"(r) : "f"(lo), "f"(hi));
  return r;
}
__device__ __forceinline__ void unpack2f(unsigned long long v, float& lo, float& hi) {
  asm("mov.b64 {%0, %1}, %2;" : "=f"(lo), "=f"(hi) : "l"(v));
}
__device__ __forceinline__ unsigned long long wpair(int k) {
  const float w = win(k);
  unsigned long long r;
  asm("mov.b64 %0, {%1, %1};" : "=l"(r) : "f"(w));
  return r;
}

// ---- cp.async staging ----
__device__ __forceinline__ void cp16(float* dst_smem, const float* src) {
  unsigned a = (unsigned)__cvta_generic_to_shared(dst_smem);
  asm volatile("cp.async.cg.shared.global [%0], [%1], 16;" :: "r"(a), "l"(src));
}
__device__ __forceinline__ void cp_commit() {
  asm volatile("cp.async.commit_group;" ::: "memory");
}
template <int N>
__device__ __forceinline__ void cp_wait_group() {
  asm volatile("cp.async.wait_group %0;" :: "n"(N) : "memory");
}

// Horizontal 11-tap conv + SSIM epilogue for 11 output columns [cbase, cbase+10].
// 21 conflict-free aligned LDS.128, compile-time taps, streaming finalization,
// paired divisions. Out-of-range outputs neutralized as (n=0, d=1) pre-division.
__device__ __forceinline__ float htask11(const unsigned long long* __restrict__ pRow,
                                         const unsigned long long* __restrict__ Wp,
                                         int cbase,
                                         unsigned long long c12,
                                         unsigned long long neg1) {
  unsigned long long hSD[11], hPQ[11];
  float acc = 0.0f, pn = 0.0f, pd = 1.0f;
#pragma unroll
  for (int c = 0; c < 21; ++c) {                       // window column, compile-time
    const ulonglong2 l2 = *reinterpret_cast<const ulonglong2*>(pRow + 2 * c);
    const unsigned long long sd = l2.x;
    const unsigned long long pq = l2.y;
#pragma unroll
    for (int m = 0; m < 11; ++m) {
      const int k = c - m;                             // tap, compile-time
      if (k == 0) {
        hSD[m] = mul2(Wp[0], sd);
        hPQ[m] = mul2(Wp[0], pq);
      } else if (k > 0 && k <= 10) {
        const int wi = (k <= 5) ? k : 10 - k;
        hSD[m] = fma2(Wp[wi], sd, hSD[m]);
        hPQ[m] = fma2(Wp[wi], pq, hPQ[m]);
      }
    }
    if (c >= 10) {                                     // output m = c-10 complete
      const int m = c - 10;
      const unsigned long long h2 = mul2(hSD[m], hSD[m]);   // (A^2, B^2)
      float a2, b2, pp, qq;
      unpack2f(h2, a2, b2);
      unpack2f(hPQ[m], pp, qq);
      const unsigned long long A = pack2f(a2, pp);
      const unsigned long long B = pack2f(b2, qq);
      const unsigned long long UE = fma2(B, neg1, A);  // (u, e) = A - B
      const unsigned long long WS = add2(A, B);        // (w, s2)
      const unsigned long long UC = add2(UE, c12);     // (u+2C1, e+2C2)
      const unsigned long long WC = add2(WS, c12);     // (w+2C1, s2+2C2)
      float u, e, w, s2, uc, ec, wc, sc;
      unpack2f(UE, u, e); (void)e;
      unpack2f(WS, w, s2); (void)s2;
      unpack2f(UC, uc, ec);
      unpack2f(WC, wc, sc);
      float num = uc * (ec - u);
      float den = wc * (sc - w);
      const bool valid = (cbase + m < OUTD);
      num = valid ? num : 0.0f;                        // SEL on ALU pipe
      den = valid ? den : 1.0f;
      if ((m & 1) == 0) { pn = num; pd = den; }
      else acc += __fdividef(pn * den + num * pd, pd * den);
    }
  }
  acc += __fdividef(pn, pd);                           // m = 10 leftover
  return acc;
}

// Shared accumulate step for one input row at phase p.
__device__ __forceinline__ void vstep(float xv, float yv, int p, int i0, bool full,
                                      const unsigned long long* __restrict__ Wp,
                                      unsigned long long pm1,
                                      unsigned long long* __restrict__ rBase,
                                      unsigned long long aSD[11],
                                      unsigned long long aPQ[11]) {
  const unsigned long long XX = pack2f(xv, xv);
  const unsigned long long YY = pack2f(yv, yv);
  const unsigned long long sd = fma2(YY, pm1, XX);     // (x+y, x-y)
  const unsigned long long pq = mul2(sd, sd);          // (s^2, d^2)
  aSD[p] = mul2(Wp[0], sd);
  aPQ[p] = mul2(Wp[0], pq);
#pragma unroll
  for (int k = 1; k < 11; ++k) {
    const int sl = (p + 11 - k) % 11;                  // compile-time
    const int wi = (k <= 5) ? k : 10 - k;
    aSD[sl] = fma2(Wp[wi], sd, aSD[sl]);
    aPQ[sl] = fma2(Wp[wi], pq, aPQ[sl]);
  }
  if (full || i0 + p >= 10) {
    const int sl = (p + 1) % 11;
    ulonglong2 v; v.x = aSD[sl]; v.y = aPQ[sl];
    *reinterpret_cast<ulonglong2*>(rBase + sl * PITCH_U) = v;   // STS.128
  }
}

// Vertical pass over one <=11-row group read from smem staging.
template <bool FULL>
__device__ __forceinline__ void vpass(const float* __restrict__ sx,
                                      const float* __restrict__ sy,
                                      unsigned long long* __restrict__ rBase,
                                      int t, int i0, int rg,
                                      const unsigned long long Wp[6],
                                      unsigned long long pm1,
                                      unsigned long long aSD[11],
                                      unsigned long long aPQ[11]) {
#pragma unroll
  for (int p = 0; p < 11; ++p) {
    if (FULL || p < rg)
      vstep(sx[p * IMG_W + t], sy[p * IMG_W + t], p, i0, FULL, Wp, pm1, rBase, aSD, aPQ);
  }
}

__global__ __launch_bounds__(512, 1)
void ssim_fused(const float* __restrict__ X, const float* __restrict__ Y,
                float* __restrict__ out) {
  extern __shared__ char smem_raw[];
  unsigned long long* ring = reinterpret_cast<unsigned long long*>(smem_raw);  // single ring
  float* stage = reinterpret_cast<float*>(ring + RING_U);                      // 3 buffers
  __shared__ float warpsum[16];
  __shared__ int sLast;

  const int img   = blockIdx.y;
  const int strip = blockIdx.x;
  const int row0  = strip * STRIP;
  const int rows  = min(STRIP, OUTD - row0);
  const int nIn   = rows + 10;
  const int ngrp  = (nIn + 10) / 11;
  const int t     = threadIdx.x;

  const float* __restrict__ Xb = X + ((size_t)img * IMG_W + row0) * IMG_W;
  const float* __restrict__ Yb = Y + ((size_t)img * IMG_W + row0) * IMG_W;

  unsigned long long Wp[6];
#pragma unroll
  for (int k = 0; k < 6; ++k) Wp[k] = wpair(k);
  const unsigned long long c12  = pack2f(TwoC1, TwoC2);
  const unsigned long long neg1 = pack2f(-1.0f, -1.0f);
  const unsigned long long pm1  = pack2f(1.0f, -1.0f);

  // Steady-state horizontal mapping: 506 tasks, slot = rq → LDS bank-quad ≡
  // t (mod 8), conflict-free for every column phase.
  const bool actS = (t < 506);
  const int  ggS  = (int)((unsigned)t / 11u);
  const int  rqS  = t - 11 * ggS;
  const int  cbS  = 11 * ggS;
  const int  rowOffS = rqS * PITCH_U + 2 * cbS;

  // Stage group g (>=1) into buffer (g-1)%3 and commit it.
  auto stage_group = [&](int g) {
    const int i0n = g * 11;
    const int rgn = min(11, nIn - i0n);
    float* dX = stage + ((g - 1) % NBUF) * STG_BUF;
    float* dY = dX + STG_CH;
    const float* sXg = Xb + (size_t)i0n * IMG_W;
    const float* sYg = Yb + (size_t)i0n * IMG_W;
    const int nch = rgn * (IMG_W / 4);
    for (int c = t; c < nch; c += 512) {
      cp16(dX + 4 * c, sXg + 4 * c);
      cp16(dY + 4 * c, sYg + 4 * c);
    }
    cp_commit();
  };

  // Prologue: commit G1, G2 (G3 committed inside group 0's slot below); G0 is
  // loaded DIRECTLY into registers — no stage wait, no barrier before compute.
  if (ngrp > 1) stage_group(1);
  if (ngrp > 2) stage_group(2);

  unsigned long long aSD[11], aPQ[11];
  unsigned long long* rBase = ring + 2 * t;
  float fsum = 0.0f;

  for (int g = 0; g < ngrp; ++g) {
    const int i0 = g * 11;
    const int rg = min(11, nIn - i0);

    if (g == 0) {
      // Group 0 from registers: 22 coalesced LDG.32, MLP=22, latency hidden
      // behind the cp.async issue burst above.
      float xv[11], yv[11];
#pragma unroll
      for (int p = 0; p < 11; ++p) {
        xv[p] = Xb[p * IMG_W + t];
        yv[p] = Yb[p * IMG_W + t];
      }
#pragma unroll
      for (int p = 0; p < 11; ++p)
        vstep(xv[p], yv[p], p, 0, false, Wp, pm1, rBase, aSD, aPQ);
    } else {
      const float* sx = stage + ((g - 1) % NBUF) * STG_BUF;
      const float* sy = sx + STG_CH;
      if (i0 >= 11 && rg == 11) vpass<true >(sx, sy, rBase, t, i0, rg, Wp, pm1, aSD, aPQ);
      else                      vpass<false>(sx, sy, rBase, t, i0, rg, Wp, pm1, aSD, aPQ);
    }
    __syncthreads();   // ring ready; stage buffer (g-1)%3 fully consumed

    // Depth-3 prefetch: G(g+3) goes into buffer (g+2)%3 — for g==0 that's the
    // untouched buf2 (G3); for g>=1 it's the buffer vpass(g) just freed.
    if (g + 3 < ngrp + (g == 0 ? 1 : 0)) { /* placeholder, see below */ }
    if (g + 3 <= ngrp - 1) stage_group(g + 3);
    else if (g == 0 && ngrp > 3) stage_group(3);   // unreachable; kept for clarity

    // Horizontal pass over output rows completed in this group.
    const int orFirst = (i0 >= 10) ? (i0 - 10) : 0;
    const int orLast  = min(i0 + rg - 11, rows - 1);
    const int rowsG   = orLast - orFirst + 1;          // 1..11
    if (rowsG == 11) {
      if (actS) fsum += htask11(ring + rowOffS, Wp, cbS, c12, neg1);
    } else {
      const int ofMod = orFirst % 11;
      if (t < 46 * rowsG) {
        const int gg = t / rowsG;
        const int rq = t - gg * rowsG;
        int slot = ofMod + rq; if (slot >= 11) slot -= 11;
        const int cb = 11 * gg;
        fsum += htask11(ring + slot * PITCH_U + 2 * cb, Wp, cb, c12, neg1);
      }
    }

    // Ensure G(g+1) landed. Commits outstanding afterward: up to
    // min(ngrp-1, g+3) − (g+1) groups.
    if (g + 1 < ngrp) {
      if (g + 3 < ngrp)      cp_wait_group<2>();
      else if (g + 2 < ngrp) cp_wait_group<1>();
      else                   cp_wait_group<0>();
    }
    __syncthreads();   // ring consumed by all; staged chunks visible to all
  }

  // Deterministic block reduction.
#pragma unroll
  for (int o = 16; o > 0; o >>= 1)
    fsum += __shfl_xor_sync(0xffffffffu, fsum, o);
  if ((t & 31) == 0) warpsum[t >> 5] = fsum;
  __syncthreads();
  if (t == 0) {
    float s = 0.0f;
#pragma unroll
    for (int wgi = 0; wgi < 16; ++wgi) s += warpsum[wgi];
    g_partials[img * NSTRIP + strip] = s;
    __threadfence();
    const unsigned v = atomicAdd(&g_done, 1u);
    sLast = (v == (unsigned)(NBLOCKS - 1));
  }
  __syncthreads();

  if (sLast) {                                 // exactly one block
    __threadfence();
    double s = 0.0;
    for (int i = t; i < NBLOCKS; i += 512) s += (double)g_partials[i];
#pragma unroll
    for (int o = 16; o > 0; o >>= 1)
      s += __shfl_xor_sync(0xffffffffu, s, o);
    __shared__ double dws[16];
    if ((t & 31) == 0) dws[t >> 5] = s;
    __syncthreads();
    if (t == 0) {
      double tot = 0.0;
#pragma unroll
      for (int wgi = 0; wgi < 16; ++wgi) tot += dws[wgi];
      out[0] = (float)(tot * (1.0 / ((double)NIMG * OUTD * OUTD)));
      g_done = 0;                              // reset for next graph replay
    }
  }
}

extern "C" void kernel_launch(void* const* d_in, const int* in_sizes, int n_in,
                              void* d_out, int out_size) {
  const float* x = (const float*)d_in[0];
  const float* y = (const float*)d_in[1];
  (void)in_sizes; (void)n_in; (void)out_size;  // window is compile-time

  static int attr_set = 0;
  if (!attr_set) {
    cudaFuncSetAttribute(ssim_fused, cudaFuncAttributeMaxDynamicSharedMemorySize,
                         SMEM_BYTES);
    attr_set = 1;
  }
  dim3 grid(NSTRIP, NIMG);
  ssim_fused<<<grid, 512, SMEM_BYTES>>>(x, y, (float*)d_out);
}

// round 16
// speedup vs baseline: 1.1793x; 1.1793x over previous
#include <cuda_runtime.h>

namespace {
constexpr int IMG_W   = 512;
constexpr int OUTD    = 502;            // 512 - 11 + 1
constexpr int NIMG    = 48;
constexpr int STRIP   = 168;            // output rows per block
constexpr int NSTRIP  = 3;              // 168+168+166 → 144 blocks = ONE wave
constexpr int PITCH_U = 1042;           // ulls per ring slot row; slot stride 8336B:
                                        // 521 quads ≡ 1 (mod 8) → with slot=rq, quad ≡ t (mod 8) → conflict-free
constexpr int RING_U  = 11 * PITCH_U;   // single interleaved ring (ulls)
constexpr int STG_CH  = 11 * IMG_W;     // floats per raw channel stage
constexpr int STG_BUF = 2 * STG_CH;     // x + y (one buffer)
constexpr int NBLOCKS = NSTRIP * NIMG;  // 144
constexpr int SMEM_BYTES = RING_U * 8 + 2 * STG_BUF * 4;  // 91696 + 90112 = 181808
constexpr float TwoC1 = 2.0e-4f;
constexpr float TwoC2 = 1.8e-3f;
}

__device__ float g_partials[NBLOCKS];
__device__ unsigned int g_done = 0;

__device__ __forceinline__ float win(int k) {
  switch (k) {
    case 0: case 10: return 0.00102838f;
    case 1: case 9:  return 0.00759873f;
    case 2: case 8:  return 0.03600078f;
    case 3: case 7:  return 0.10936070f;
    case 4: case 6:  return 0.21300553f;
    default:         return 0.26601176f;
  }
}

// ---- packed f32x2 helpers ----
__device__ __forceinline__ unsigned long long mul2(unsigned long long a, unsigned long long b) {
  unsigned long long r;
  asm("mul.rn.f32x2 %0, %1, %2;" : "=l"(r) : "l"(a), "l"(b));
  return r;
}
__device__ __forceinline__ unsigned long long add2(unsigned long long a, unsigned long long b) {
  unsigned long long r;
  asm("add.rn.f32x2 %0, %1, %2;" : "=l"(r) : "l"(a), "l"(b));
  return r;
}
__device__ __forceinline__ unsigned long long fma2(unsigned long long a, unsigned long long b,
                                                   unsigned long long c) {
  unsigned long long r;
  asm("fma.rn.f32x2 %0, %1, %2, %3;" : "=l"(r) : "l"(a), "l"(b), "l"(c));
  return r;
}
__device__ __forceinline__ unsigned long long pack2f(float lo, float hi) {
  unsigned long long r;
  asm("mov.b64 %0, {%1, %2};" : "=l"(r) : "f"(lo), "f"(hi));
  return r;
}
__device__ __forceinline__ void unpack2f(unsigned long long v, float& lo, float& hi) {
  asm("mov.b64 {%0, %1}, %2;" : "=f"(lo), "=f"(hi) : "l"(v));
}
__device__ __forceinline__ unsigned long long wpair(int k) {
  const float w = win(k);
  unsigned long long r;
  asm("mov.b64 %0, {%1, %1};" : "=l"(r) : "f"(w));
  return r;
}

// ---- cp.async staging ----
__device__ __forceinline__ void cp16(float* dst_smem, const float* src) {
  unsigned a = (unsigned)__cvta_generic_to_shared(dst_smem);
  asm volatile("cp.async.cg.shared.global [%0], [%1], 16;" :: "r"(a), "l"(src));
}
__device__ __forceinline__ void cp_commit() {
  asm volatile("cp.async.commit_group;" ::: "memory");
}
template <int N>
__device__ __forceinline__ void cp_wait_group() {
  asm volatile("cp.async.wait_group %0;" :: "n"(N) : "memory");
}

// Horizontal 11-tap conv + SSIM epilogue for 11 output columns [cbase, cbase+10].
// 21 conflict-free aligned LDS.128, compile-time taps, streaming finalization,
// paired divisions. Out-of-range outputs neutralized as (n=0, d=1) pre-division.
__device__ __forceinline__ float htask11(const unsigned long long* __restrict__ pRow,
                                         const unsigned long long* __restrict__ Wp,
                                         int cbase,
                                         unsigned long long c12,
                                         unsigned long long neg1) {
  unsigned long long hSD[11], hPQ[11];
  float acc = 0.0f, pn = 0.0f, pd = 1.0f;
#pragma unroll
  for (int c = 0; c < 21; ++c) {                       // window column, compile-time
    const ulonglong2 l2 = *reinterpret_cast<const ulonglong2*>(pRow + 2 * c);
    const unsigned long long sd = l2.x;
    const unsigned long long pq = l2.y;
#pragma unroll
    for (int m = 0; m < 11; ++m) {
      const int k = c - m;                             // tap, compile-time
      if (k == 0) {
        hSD[m] = mul2(Wp[0], sd);
        hPQ[m] = mul2(Wp[0], pq);
      } else if (k > 0 && k <= 10) {
        const int wi = (k <= 5) ? k : 10 - k;
        hSD[m] = fma2(Wp[wi], sd, hSD[m]);
        hPQ[m] = fma2(Wp[wi], pq, hPQ[m]);
      }
    }
    if (c >= 10) {                                     // output m = c-10 complete
      const int m = c - 10;
      const unsigned long long h2 = mul2(hSD[m], hSD[m]);   // (A^2, B^2)
      float a2, b2, pp, qq;
      unpack2f(h2, a2, b2);
      unpack2f(hPQ[m], pp, qq);
      const unsigned long long A = pack2f(a2, pp);
      const unsigned long long B = pack2f(b2, qq);
      const unsigned long long UE = fma2(B, neg1, A);  // (u, e) = A - B
      const unsigned long long WS = add2(A, B);        // (w, s2)
      const unsigned long long UC = add2(UE, c12);     // (u+2C1, e+2C2)
      const unsigned long long WC = add2(WS, c12);     // (w+2C1, s2+2C2)
      float u, e, w, s2, uc, ec, wc, sc;
      unpack2f(UE, u, e); (void)e;
      unpack2f(WS, w, s2); (void)s2;
      unpack2f(UC, uc, ec);
      unpack2f(WC, wc, sc);
      float num = uc * (ec - u);
      float den = wc * (sc - w);
      const bool valid = (cbase + m < OUTD);
      num = valid ? num : 0.0f;                        // SEL on ALU pipe
      den = valid ? den : 1.0f;
      if ((m & 1) == 0) { pn = num; pd = den; }
      else acc += __fdividef(pn * den + num * pd, pd * den);
    }
  }
  acc += __fdividef(pn, pd);                           // m = 10 leftover
  return acc;
}

// One vertical accumulate step for input row at phase p.
__device__ __forceinline__ void vstep(float xv, float yv, int p, int i0, bool full,
                                      const unsigned long long* __restrict__ Wp,
                                      unsigned long long pm1,
                                      unsigned long long* __restrict__ rBase,
                                      unsigned long long aSD[11],
                                      unsigned long long aPQ[11]) {
  const unsigned long long XX = pack2f(xv, xv);
  const unsigned long long YY = pack2f(yv, yv);
  const unsigned long long sd = fma2(YY, pm1, XX);     // (x+y, x-y)
  const unsigned long long pq = mul2(sd, sd);          // (s^2, d^2)
  aSD[p] = mul2(Wp[0], sd);
  aPQ[p] = mul2(Wp[0], pq);
#pragma unroll
  for (int k = 1; k < 11; ++k) {
    const int sl = (p + 11 - k) % 11;                  // compile-time
    const int wi = (k <= 5) ? k : 10 - k;
    aSD[sl] = fma2(Wp[wi], sd, aSD[sl]);
    aPQ[sl] = fma2(Wp[wi], pq, aPQ[sl]);
  }
  if (full || i0 + p >= 10) {
    const int sl = (p + 1) % 11;
    ulonglong2 v; v.x = aSD[sl]; v.y = aPQ[sl];
    *reinterpret_cast<ulonglong2*>(rBase + sl * PITCH_U) = v;   // STS.128
  }
}

// Vertical pass over one <=11-row group read from smem staging.
template <bool FULL>
__device__ __forceinline__ void vpass(const float* __restrict__ sx,
                                      const float* __restrict__ sy,
                                      unsigned long long* __restrict__ rBase,
                                      int t, int i0, int rg,
                                      const unsigned long long Wp[6],
                                      unsigned long long pm1,
                                      unsigned long long aSD[11],
                                      unsigned long long aPQ[11]) {
#pragma unroll
  for (int p = 0; p < 11; ++p) {
    if (FULL || p < rg)
      vstep(sx[p * IMG_W + t], sy[p * IMG_W + t], p, i0, FULL, Wp, pm1, rBase, aSD, aPQ);
  }
}

__global__ __launch_bounds__(512, 1)
void ssim_fused(const float* __restrict__ X, const float* __restrict__ Y,
                float* __restrict__ out) {
  extern __shared__ char smem_raw[];
  unsigned long long* ring = reinterpret_cast<unsigned long long*>(smem_raw);  // single ring
  float* stage = reinterpret_cast<float*>(ring + RING_U);                      // 2 buffers
  __shared__ float warpsum[16];
  __shared__ int sLast;

  const int img   = blockIdx.y;
  const int strip = blockIdx.x;
  const int row0  = strip * STRIP;
  const int rows  = min(STRIP, OUTD - row0);
  const int nIn   = rows + 10;
  const int ngrp  = (nIn + 10) / 11;
  const int t     = threadIdx.x;

  const float* __restrict__ Xb = X + ((size_t)img * IMG_W + row0) * IMG_W;
  const float* __restrict__ Yb = Y + ((size_t)img * IMG_W + row0) * IMG_W;

  // G0 register loads FIRST — they take the front of the L1tex queue, ahead of
  // the cp.async burst below (queue is FIFO; issuing them after the DMA commits
  // was the R15 regression).
  float xv0[11], yv0[11];
#pragma unroll
  for (int p = 0; p < 11; ++p) {
    xv0[p] = Xb[p * IMG_W + t];
    yv0[p] = Yb[p * IMG_W + t];
  }

  // Stage group g (>=1) into buffer (g&1) and commit it.
  auto stage_group = [&](int g) {
    const int i0n = g * 11;
    const int rgn = min(11, nIn - i0n);
    float* dX = stage + (g & 1) * STG_BUF;
    float* dY = dX + STG_CH;
    const float* sXg = Xb + (size_t)i0n * IMG_W;
    const float* sYg = Yb + (size_t)i0n * IMG_W;
    const int nch = rgn * (IMG_W / 4);
    for (int c = t; c < nch; c += 512) {
      cp16(dX + 4 * c, sXg + 4 * c);
      cp16(dY + 4 * c, sYg + 4 * c);
    }
    cp_commit();
  };

  // Commit G1 now; it streams behind G0's register loads during group-0 compute.
  if (ngrp > 1) stage_group(1);

  unsigned long long Wp[6];
#pragma unroll
  for (int k = 0; k < 6; ++k) Wp[k] = wpair(k);
  const unsigned long long c12  = pack2f(TwoC1, TwoC2);
  const unsigned long long neg1 = pack2f(-1.0f, -1.0f);
  const unsigned long long pm1  = pack2f(1.0f, -1.0f);

  // Steady-state horizontal mapping: 506 tasks, slot = rq → LDS bank-quad ≡
  // t (mod 8), conflict-free for every column phase.
  const bool actS = (t < 506);
  const int  ggS  = (int)((unsigned)t / 11u);
  const int  rqS  = t - 11 * ggS;
  const int  cbS  = 11 * ggS;
  const int  rowOffS = rqS * PITCH_U + 2 * cbS;

  unsigned long long aSD[11], aPQ[11];
  unsigned long long* rBase = ring + 2 * t;
  float fsum = 0.0f;

  for (int g = 0; g < ngrp; ++g) {
    const int i0 = g * 11;
    const int rg = min(11, nIn - i0);

    if (g == 0) {
      // Group 0 from registers (loads issued at kernel entry; no stage wait).
#pragma unroll
      for (int p = 0; p < 11; ++p)
        vstep(xv0[p], yv0[p], p, 0, false, Wp, pm1, rBase, aSD, aPQ);
    } else {
      const float* sx = stage + (g & 1) * STG_BUF;
      const float* sy = sx + STG_CH;
      if (i0 >= 11 && rg == 11) vpass<true >(sx, sy, rBase, t, i0, rg, Wp, pm1, aSD, aPQ);
      else                      vpass<false>(sx, sy, rBase, t, i0, rg, Wp, pm1, aSD, aPQ);
    }
    __syncthreads();   // ring ready; stage buffer (g&1) fully consumed

    // Depth-2 prefetch: G(g+2) reuses the buffer of matching parity (for g=0
    // that's buf0, which G0 never touched).
    if (g + 2 < ngrp) stage_group(g + 2);

    // Horizontal pass over output rows completed in this group.
    const int orFirst = (i0 >= 10) ? (i0 - 10) : 0;
    const int orLast  = min(i0 + rg - 11, rows - 1);
    const int rowsG   = orLast - orFirst + 1;          // 1..11
    if (rowsG == 11) {
      if (actS) fsum += htask11(ring + rowOffS, Wp, cbS, c12, neg1);
    } else {
      const int ofMod = orFirst % 11;
      if (t < 46 * rowsG) {
        const int gg = t / rowsG;
        const int rq = t - gg * rowsG;
        int slot = ofMod + rq; if (slot >= 11) slot -= 11;
        const int cb = 11 * gg;
        fsum += htask11(ring + slot * PITCH_U + 2 * cb, Wp, cb, c12, neg1);
      }
    }

    // Ensure G(g+1) landed. Pending afterward: {G(g+1), G(g+2)} → wait<1>;
    // {G(g+1)} only → wait<0>.
    if (g + 1 < ngrp) {
      if (g + 2 < ngrp) cp_wait_group<1>();
      else              cp_wait_group<0>();
    }
    __syncthreads();   // ring consumed by all; staged chunks visible to all
  }

  // Deterministic block reduction.
#pragma unroll
  for (int o = 16; o > 0; o >>= 1)
    fsum += __shfl_xor_sync(0xffffffffu, fsum, o);
  if ((t & 31) == 0) warpsum[t >> 5] = fsum;
  __syncthreads();
  if (t == 0) {
    float s = 0.0f;
#pragma unroll
    for (int wgi = 0; wgi < 16; ++wgi) s += warpsum[wgi];
    g_partials[img * NSTRIP + strip] = s;
    __threadfence();
    const unsigned v = atomicAdd(&g_done, 1u);
    sLast = (v == (unsigned)(NBLOCKS - 1));
  }
  __syncthreads();

  if (sLast) {                                 // exactly one block
    __threadfence();
    double s = 0.0;
    for (int i = t; i < NBLOCKS; i += 512) s += (double)g_partials[i];
#pragma unroll
    for (int o = 16; o > 0; o >>= 1)
      s += __shfl_xor_sync(0xffffffffu, s, o);
    __shared__ double dws[16];
    if ((t & 31) == 0) dws[t >> 5] = s;
    __syncthreads();
    if (t == 0) {
      double tot = 0.0;
#pragma unroll
      for (int wgi = 0; wgi < 16; ++wgi) tot += dws[wgi];
      out[0] = (float)(tot * (1.0 / ((double)NIMG * OUTD * OUTD)));
      g_done = 0;                              // reset for next graph replay
    }
  }
}

extern "C" void kernel_launch(void* const* d_in, const int* in_sizes, int n_in,
                              void* d_out, int out_size) {
  const float* x = (const float*)d_in[0];
  const float* y = (const float*)d_in[1];
  (void)in_sizes; (void)n_in; (void)out_size;  // window is compile-time

  static int attr_set = 0;
  if (!attr_set) {
    cudaFuncSetAttribute(ssim_fused, cudaFuncAttributeMaxDynamicSharedMemorySize,
                         SMEM_BYTES);
    attr_set = 1;
  }
  dim3 grid(NSTRIP, NIMG);
  ssim_fused<<<grid, 512, SMEM_BYTES>>>(x, y, (float*)d_out);
}